// round 10
// baseline (speedup 1.0000x reference)
#include <cuda_runtime.h>
#include <cuda_bf16.h>
#include <cstdint>

// Problem constants (fixed by the reference)
#define N_COLS  22
#define N_PAIRS 231
#define EMB     12
#define DVEC    64
#define N_PRIM  5
#define COMBO2  (EMB * EMB * 2)   // 288 floats per pair in the LUT
#define NCHUNK  8                 // pair-dimension split for kernel 2
#define CHUNKSZ ((N_PAIRS + NCHUNK - 1) / NCHUNK)   // 29
#define SLICE0  (4 * CHUNKSZ)     // 116: pair boundary between pipeline stages

// Pair index table, computed on host, passed by value (constant bank)
struct PairTab { uchar2 ij[N_PAIRS]; };

// Scratch: precomputed per-pair lookup table T[p][fi][fj][o]  (266 KB)
__device__ __align__(16) float g_T[N_PAIRS * COMBO2];

// ---------------------------------------------------------------------------
// Kernel 1 (sliced): warp-per-(p, fi). No SMEM, no __syncthreads.
// 16-lane halves: lane hl holds dims 4hl..4hl+3 (float4). Half h computes
// fj = 2t+h for t=0..5. Coalesced LDG.128 from L2-hot tables; 16-lane
// shuffle reductions. Slice 0 also zero-initializes out[].
// ---------------------------------------------------------------------------
__global__ __launch_bounds__(256)
void build_lut_kernel(const float* __restrict__ tables,
                      const float* __restrict__ Wsmall,
                      const float* __restrict__ Wconcat,
                      const float* __restrict__ aw,
                      float* __restrict__ out, int outN,   // outN=0 -> no zeroing
                      int pairBase, int nPairs,
                      const PairTab tab)
{
    // zero the output buffer (poisoned by harness) — slice 0 only
    {
        const int gz = blockIdx.x * 256 + threadIdx.x;
        if (gz < outN) out[gz] = 0.0f;
    }

    const int gwarp = (blockIdx.x * 256 + threadIdx.x) >> 5;
    if (gwarp >= nPairs * EMB) return;

    const int p    = pairBase + gwarp / EMB;
    const int fi   = gwarp % EMB;
    const int lane = threadIdx.x & 31;
    const int half = lane >> 4;          // 0 or 1
    const int hl   = lane & 15;          // lane within half

    const int i = tab.ij[p].x;
    const int j = tab.ij[p].y;

    // selected primitive via one ballot (arch_weights is exact one-hot 0/1)
    const bool hot = (lane < N_PRIM) && (__ldg(&aw[p * N_PRIM + lane]) > 0.5f);
    const int  k   = __ffs(__ballot_sync(0xffffffffu, hot)) - 1;

    const float4* __restrict__ t4 = (const float4*)tables;
    const float4 Pi = __ldg(&t4[(i * EMB + fi) * (DVEC / 4) + hl]);

    float4 w0, w1;          // weights over this lane's 4 dims, o = 0 / 1
    float  pp0 = 0.0f, pp1 = 0.0f;   // reduced P-part for concat
    if (k == 4) {
        const float4* __restrict__ wc = (const float4*)(Wconcat + p * 2 * (2 * DVEC));
        const float4 a0 = __ldg(&wc[hl]);            // o=0, P dims
        const float4 a1 = __ldg(&wc[32 + hl]);       // o=1, P dims
        w0 = __ldg(&wc[16 + hl]);                    // o=0, Q dims
        w1 = __ldg(&wc[48 + hl]);                    // o=1, Q dims
        pp0 = a0.x * Pi.x + a0.y * Pi.y + a0.z * Pi.z + a0.w * Pi.w;
        pp1 = a1.x * Pi.x + a1.y * Pi.y + a1.z * Pi.z + a1.w * Pi.w;
#pragma unroll
        for (int off = 8; off; off >>= 1) {
            pp0 += __shfl_xor_sync(0xffffffffu, pp0, off);
            pp1 += __shfl_xor_sync(0xffffffffu, pp1, off);
        }
    } else {
        const float4* __restrict__ ws = (const float4*)(Wsmall + (p * 4 + k) * 2 * DVEC);
        w0 = __ldg(&ws[hl]);
        w1 = __ldg(&ws[16 + hl]);
    }

    float2* __restrict__ T2 = (float2*)g_T;

#pragma unroll
    for (int t = 0; t < 6; ++t) {
        const int fj = t * 2 + half;
        const float4 Q = __ldg(&t4[(j * EMB + fj) * (DVEC / 4) + hl]);

        float4 z;
        if (k == 0)      { z.x = Pi.x + Q.x; z.y = Pi.y + Q.y; z.z = Pi.z + Q.z; z.w = Pi.w + Q.w; }
        else if (k == 1) { z.x = Pi.x * Q.x; z.y = Pi.y * Q.y; z.z = Pi.z * Q.z; z.w = Pi.w * Q.w; }
        else if (k == 2) { z.x = fmaxf(Pi.x, Q.x); z.y = fmaxf(Pi.y, Q.y); z.z = fmaxf(Pi.z, Q.z); z.w = fmaxf(Pi.w, Q.w); }
        else if (k == 3) { z.x = fminf(Pi.x, Q.x); z.y = fminf(Pi.y, Q.y); z.z = fminf(Pi.z, Q.z); z.w = fminf(Pi.w, Q.w); }
        else             { z = Q; }   // concat: Q-part only; P-part already reduced

        float s0 = z.x * w0.x + z.y * w0.y + z.z * w0.z + z.w * w0.w;
        float s1 = z.x * w1.x + z.y * w1.y + z.z * w1.z + z.w * w1.w;
#pragma unroll
        for (int off = 8; off; off >>= 1) {
            s0 += __shfl_xor_sync(0xffffffffu, s0, off);
            s1 += __shfl_xor_sync(0xffffffffu, s1, off);
        }
        if (k == 4) { s0 += pp0; s1 += pp1; }

        if (hl == 0)
            T2[p * (EMB * EMB) + fi * EMB + fj] = make_float2(s0, s1);
    }
}

// ---------------------------------------------------------------------------
// Kernel 2 (chunk group): out[b, :] += sum_{p in chunk} T[p, f[i_p], f[j_p], :]
// grid = (B/32) x 4 chunks per group. lane = batch element; warp w strides
// its chunk's 29 pairs (<=4 independent unrolled gathers). All 32 lanes
// gather inside ONE pair's 1.15 KB LUT region (L1-coherent).
// Cross-warp SMEM reduce, then atomicAdd (out zeroed by k1 slice 0).
// ---------------------------------------------------------------------------
__global__ __launch_bounds__(256)
void accumulate_kernel(const int* __restrict__ feats,
                       float* __restrict__ out,
                       int B, int chunkBase,
                       const PairTab tab)
{
    __shared__ int    shf[32][N_COLS + 1];   // stride 23: coprime with 32 banks
    __shared__ float2 shred[8][32];

    const int tid   = threadIdx.x;
    const int lane  = tid & 31;
    const int warp  = tid >> 5;
    const int bbase = blockIdx.x * 32;
    const int p0    = (chunkBase + blockIdx.y) * CHUNKSZ;
    const int npair = min(N_PAIRS - p0, CHUNKSZ);

    // coalesced, cooperative load of this block's 32 feats rows
    for (int e = tid; e < 32 * N_COLS; e += 256) {
        const int row = e / N_COLS, col = e - row * N_COLS;
        const int b   = bbase + row;
        shf[row][col] = (b < B) ? feats[b * N_COLS + col] : 0;
    }
    __syncthreads();

    const float2* __restrict__ T2 = (const float2*)g_T;
    float ax = 0.0f, ay = 0.0f;

    // warp w handles chunk-local pairs w, w+8, ... (<= 4 independent gathers)
#pragma unroll 4
    for (int t = warp; t < npair; t += 8) {
        const uchar2 ij = tab.ij[p0 + t];        // constant bank, uniform
        const int fi = shf[lane][ij.x];
        const int fj = shf[lane][ij.y];
        const float2 v = __ldg(&T2[(p0 + t) * (EMB * EMB) + fi * EMB + fj]);
        ax += v.x;
        ay += v.y;
    }

    shred[warp][lane] = make_float2(ax, ay);
    __syncthreads();

    if (warp == 0) {
        float sx = 0.0f, sy = 0.0f;
#pragma unroll
        for (int w = 0; w < 8; ++w) {
            const float2 s = shred[w][lane];
            sx += s.x;
            sy += s.y;
        }
        const int b = bbase + lane;
        if (b < B) {
            atomicAdd(&out[b * 2 + 0], sx);
            atomicAdd(&out[b * 2 + 1], sy);
        }
    }
}

// ---------------------------------------------------------------------------
// Launch: two-stream fork-join pipeline (graph-capturable).
//   stream0: k1[0,116)  e1  k1[116,231)  e2            ... join e3
//   s2:      wait e1 -> k2 chunks 0-3 -> wait e2 -> k2 chunks 4-7 -> e3
// Handles are created per call and intentionally not destroyed (kernel_launch
// only runs a handful of times on the host; graph replays re-execute none of
// this). Inputs: feats(i32), tables(f32), W_small, W_concat, arch_weights.
// ---------------------------------------------------------------------------
extern "C" void kernel_launch(void* const* d_in, const int* in_sizes, int n_in,
                              void* d_out, int out_size)
{
    const int*   feats   = (const int*)  d_in[0];
    const float* tables  = (const float*)d_in[1];
    const float* Wsmall  = (const float*)d_in[2];
    const float* Wconcat = (const float*)d_in[3];
    const float* aw      = (const float*)d_in[4];
    float*       out     = (float*)d_out;

    const int B = in_sizes[0] / N_COLS;   // 4096

    // host-side triu(N_COLS, 1) pair table -> constant-bank kernel param
    PairTab tab;
    {
        int p = 0;
        for (int i = 0; i < N_COLS; ++i)
            for (int j = i + 1; j < N_COLS; ++j, ++p)
                tab.ij[p] = make_uchar2((unsigned char)i, (unsigned char)j);
    }

    cudaStream_t s2;
    cudaStreamCreateWithFlags(&s2, cudaStreamNonBlocking);
    cudaEvent_t e1, e2, e3;
    cudaEventCreateWithFlags(&e1, cudaEventDisableTiming);
    cudaEventCreateWithFlags(&e2, cudaEventDisableTiming);
    cudaEventCreateWithFlags(&e3, cudaEventDisableTiming);

    const int np0 = SLICE0;             // 116 pairs -> chunks 0..3
    const int np1 = N_PAIRS - SLICE0;   // 115 pairs -> chunks 4..7
    const int blk0 = (np0 * EMB + 7) / 8;   // 8 warps/block
    const int blk1 = (np1 * EMB + 7) / 8;

    // stream 0: LUT slices
    build_lut_kernel<<<blk0, 256>>>(tables, Wsmall, Wconcat, aw,
                                    out, out_size, 0, np0, tab);
    cudaEventRecord(e1, 0);
    build_lut_kernel<<<blk1, 256>>>(tables, Wsmall, Wconcat, aw,
                                    out, 0, SLICE0, np1, tab);
    cudaEventRecord(e2, 0);

    // s2: accumulate groups, pipelined against stream 0
    dim3 grid((B + 31) / 32, 4);
    cudaStreamWaitEvent(s2, e1, 0);
    accumulate_kernel<<<grid, 256, 0, s2>>>(feats, out, B, 0, tab);
    cudaStreamWaitEvent(s2, e2, 0);
    accumulate_kernel<<<grid, 256, 0, s2>>>(feats, out, B, 4, tab);
    cudaEventRecord(e3, s2);

    // join back to the origin stream so downstream capture sees completion
    cudaStreamWaitEvent(0, e3, 0);
}